// round 15
// baseline (speedup 1.0000x reference)
#include <cuda_runtime.h>
#include <cuda_fp16.h>
#include <cstdint>

// Problem constants
#define BATCH 2
#define SEQN  8192
#define DMODEL 512
#define HEADS 8
#define DK 64
#define KNN 32
#define MROWS (BATCH*SEQN)   // 16384
#define LN_EPS 1e-5f
#define NW (DMODEL*DMODEL)   // 262144
#define NX (MROWS*DMODEL)    // 8388608

// ---------------- scratch (device globals; no allocation allowed) -------------
__device__ __align__(128) __half g_Q[NX];
__device__ __align__(128) __half g_K[NX];
__device__ __align__(128) __half g_V[NX];
__device__ __align__(128) __half g_xh[NX];        // x in fp16
__device__ __align__(128) __half g_ah[NX];        // attention out in fp16
__device__ __align__(128) __half g_wh[4 * NW];    // weights fp16

// ---------------- small helpers -------------------------------------------------
__device__ __forceinline__ uint32_t smem_u32(const void* p) {
    uint32_t a;
    asm("{ .reg .u64 t; cvta.to.shared.u64 t, %1; cvt.u32.u64 %0, t; }"
        : "=r"(a) : "l"(p));
    return a;
}
__device__ __forceinline__ void ldsm_x4(uint32_t (&r)[4], uint32_t addr) {
    asm volatile("ldmatrix.sync.aligned.m8n8.x4.shared.b16 {%0,%1,%2,%3}, [%4];"
                 : "=r"(r[0]), "=r"(r[1]), "=r"(r[2]), "=r"(r[3]) : "r"(addr));
}
__device__ __forceinline__ void mma16816(float (&c)[4], const uint32_t (&a)[4],
                                         const uint32_t b0, const uint32_t b1) {
    asm volatile("mma.sync.aligned.m16n8k16.row.col.f32.f16.f16.f32 "
                 "{%0,%1,%2,%3}, {%4,%5,%6,%7}, {%8,%9}, {%0,%1,%2,%3};"
                 : "+f"(c[0]), "+f"(c[1]), "+f"(c[2]), "+f"(c[3])
                 : "r"(a[0]), "r"(a[1]), "r"(a[2]), "r"(a[3]), "r"(b0), "r"(b1));
}
__device__ __forceinline__ void cp16(uint32_t saddr, const void* gaddr) {
    asm volatile("cp.async.cg.shared.global [%0], [%1], 16;"
                 :: "r"(saddr), "l"(gaddr) : "memory");
}
#define CP_COMMIT() asm volatile("cp.async.commit_group;" ::: "memory")
#define CP_WAIT1()  asm volatile("cp.async.wait_group 1;" ::: "memory")
#define CP_WAIT0()  asm volatile("cp.async.wait_group 0;" ::: "memory")

__device__ __forceinline__ float warp_sum(float v) {
    v += __shfl_xor_sync(0xffffffffu, v, 16);
    v += __shfl_xor_sync(0xffffffffu, v, 8);
    v += __shfl_xor_sync(0xffffffffu, v, 4);
    v += __shfl_xor_sync(0xffffffffu, v, 2);
    v += __shfl_xor_sync(0xffffffffu, v, 1);
    return v;
}
__device__ __forceinline__ float warp_max(float v) {
    v = fmaxf(v, __shfl_xor_sync(0xffffffffu, v, 16));
    v = fmaxf(v, __shfl_xor_sync(0xffffffffu, v, 8));
    v = fmaxf(v, __shfl_xor_sync(0xffffffffu, v, 4));
    v = fmaxf(v, __shfl_xor_sync(0xffffffffu, v, 2));
    v = fmaxf(v, __shfl_xor_sync(0xffffffffu, v, 1));
    return v;
}

// ---------------- GEMM: C_t = A(16384x512,fp16) * W_t^T (single fp16 W) ---------
// CTA tile 128(M) x 128(N), BK=64, 8 warps (4m x 2n), warp tile 32x64.
// 3-stage cp.async, 110.6 KB smem -> 2 CTAs/SM (prologue/epilogue overlap).
// OUT_HALF: fp16 vs fp32 output. DO_LN: fused 64-col LayerNorm (tmat 0 x1/8, 1).
#define BKC 64
#define NCH (DMODEL / BKC)     // 8
#define PITCH 72               // fp16/row (144B; 144 mod 128 = 16 -> ldsm conflict-free)
#define TILE_A_B (128 * PITCH * 2)      // 18432 B
#define TILE_B_B (128 * PITCH * 2)      // 18432 B
#define STAGE_B (TILE_A_B + TILE_B_B)   // 36864 B
#define NSTAGE 3
#define GEMM_SMEM (NSTAGE * STAGE_B)    // 110592 B

template <int OUT_HALF, int DO_LN>
__global__ __launch_bounds__(256, 2)
void gemm_f16(const __half* __restrict__ A, const __half* __restrict__ Wh,
              void* __restrict__ C0, void* __restrict__ C1, void* __restrict__ C2,
              const float* __restrict__ bias)
{
    extern __shared__ char smem[];
    const uint32_t sbase = smem_u32(smem);
    const int tid  = threadIdx.x;
    const int wid  = tid >> 5;
    const int lane = tid & 31;

    const int tmat = blockIdx.x >> 2;
    const int bnn  = (blockIdx.x & 3) * 128;
    const int bm   = blockIdx.y * 128;
    const int warp_m = wid & 3;          // 0..3 (32 rows each)
    const int warp_n = wid >> 2;         // 0..1 (64 cols each)

    const __half* Bh = Wh + (size_t)tmat * NW;
    void* C = (tmat == 0) ? C0 : (tmat == 1) ? C1 : C2;

    const int lr = tid >> 3;             // 0..31
    const int lc = tid & 7;              // 16B chunk (8 per 128B row)

    auto load_stage = [&](int c, int buf) {
        const uint32_t s0 = sbase + buf * STAGE_B;
        const int kc = c * BKC;
        #pragma unroll
        for (int p = 0; p < 4; ++p) {    // A: 128 rows
            const int r = lr + p * 32;
            cp16(s0 + (uint32_t)(r * (PITCH * 2) + lc * 16),
                 A + (size_t)(bm + r) * DMODEL + kc + lc * 8);
        }
        #pragma unroll
        for (int p = 0; p < 4; ++p) {    // B: 128 rows
            const int r = lr + p * 32;
            cp16(s0 + TILE_A_B + (uint32_t)(r * (PITCH * 2) + lc * 16),
                 Bh + (size_t)(bnn + r) * DMODEL + kc + lc * 8);
        }
        CP_COMMIT();
    };

    float acc[2][8][4];
    #pragma unroll
    for (int i = 0; i < 2; i++)
        #pragma unroll
        for (int j = 0; j < 8; j++)
            #pragma unroll
            for (int r = 0; r < 4; r++) acc[i][j][r] = 0.f;

    load_stage(0, 0);
    load_stage(1, 1);

    const int aRow  = lane & 15;
    const int aColB = (lane >> 4) * 8;
    const int quad  = lane >> 3;
    const int bRowL = (quad >> 1) * 8 + (lane & 7);
    const int bColB = (quad & 1) * 8;

    #pragma unroll 1
    for (int c = 0; c < NCH; ++c) {
        const int buf = c % NSTAGE;
        if (c + 1 < NCH) CP_WAIT1(); else CP_WAIT0();
        __syncthreads();
        if (c + 2 < NCH) load_stage(c + 2, (c + 2) % NSTAGE);

        const uint32_t sA  = sbase + buf * STAGE_B;
        const uint32_t sBh = sA + TILE_A_B;

        #pragma unroll
        for (int ks = 0; ks < 4; ++ks) {    // 4 k16 steps per 64-col chunk
            uint32_t af[2][4];
            uint32_t bfr[8][2];
            #pragma unroll
            for (int i = 0; i < 2; ++i) {
                const uint32_t ao = (uint32_t)((warp_m * 32 + i * 16 + aRow) * PITCH
                                               + ks * 16 + aColB) * 2;
                ldsm_x4(af[i], sA + ao);
            }
            #pragma unroll
            for (int p = 0; p < 4; ++p) {
                const uint32_t bo = (uint32_t)((warp_n * 64 + p * 16 + bRowL) * PITCH
                                               + ks * 16 + bColB) * 2;
                uint32_t r0[4];
                ldsm_x4(r0, sBh + bo);
                bfr[2*p][0]   = r0[0]; bfr[2*p][1]   = r0[1];
                bfr[2*p+1][0] = r0[2]; bfr[2*p+1][1] = r0[3];
            }
            #pragma unroll
            for (int i = 0; i < 2; ++i)
                #pragma unroll
                for (int j = 0; j < 8; ++j)
                    mma16816(acc[i][j], af[i], bfr[j][0], bfr[j][1]);
        }
    }

    // fused LayerNorm over the 64-col head group (warp tile N == head group).
    if (DO_LN && tmat <= 1) {
        const float qscale = (tmat == 0) ? 0.125f : 1.0f;
        #pragma unroll
        for (int i = 0; i < 2; ++i) {
            #pragma unroll
            for (int hf = 0; hf < 2; ++hf) {
                float s = 0.f, s2 = 0.f;
                #pragma unroll
                for (int j = 0; j < 8; ++j) {
                    const float c0 = acc[i][j][hf * 2], c1 = acc[i][j][hf * 2 + 1];
                    s += c0 + c1;
                    s2 += c0 * c0 + c1 * c1;
                }
                s  += __shfl_xor_sync(0xffffffffu, s, 1);
                s  += __shfl_xor_sync(0xffffffffu, s, 2);
                s2 += __shfl_xor_sync(0xffffffffu, s2, 1);
                s2 += __shfl_xor_sync(0xffffffffu, s2, 2);
                const float mean = s * (1.f / 64.f);
                const float var  = s2 * (1.f / 64.f) - mean * mean;
                const float rr   = rsqrtf(var + LN_EPS) * qscale;
                #pragma unroll
                for (int j = 0; j < 8; ++j) {
                    acc[i][j][hf * 2]     = (acc[i][j][hf * 2]     - mean) * rr;
                    acc[i][j][hf * 2 + 1] = (acc[i][j][hf * 2 + 1] - mean) * rr;
                }
            }
        }
    }

    // epilogue
    const int mBase = bm + warp_m * 32 + (lane >> 2);
    const int nBase = bnn + warp_n * 64 + (lane & 3) * 2;
    #pragma unroll
    for (int i = 0; i < 2; ++i) {
        #pragma unroll
        for (int j = 0; j < 8; ++j) {
            const int row = mBase + i * 16;
            const int col = nBase + j * 8;
            float2 v0 = make_float2(acc[i][j][0], acc[i][j][1]);
            float2 v1 = make_float2(acc[i][j][2], acc[i][j][3]);
            if (bias) {
                const float b0 = bias[col], b1 = bias[col + 1];
                v0.x += b0; v0.y += b1; v1.x += b0; v1.y += b1;
            }
            if (OUT_HALF) {
                __half* Ch = (__half*)C;
                *(__half2*)(Ch + (size_t)row * DMODEL + col) =
                    __floats2half2_rn(v0.x, v0.y);
                *(__half2*)(Ch + (size_t)(row + 8) * DMODEL + col) =
                    __floats2half2_rn(v1.x, v1.y);
            } else {
                float* Cf = (float*)C;
                *(float2*)(Cf + (size_t)row * DMODEL + col)       = v0;
                *(float2*)(Cf + (size_t)(row + 8) * DMODEL + col) = v1;
            }
        }
    }
}

// ---------------- fp32 -> fp16 (single) ------------------------------------------
__global__ void cvt_h(const float* __restrict__ s, __half* __restrict__ d)
{
    int i = (blockIdx.x * blockDim.x + threadIdx.x) * 4;
    float4 v = *(const float4*)(s + i);
    __half2* p = (__half2*)(d + i);
    p[0] = __floats2half2_rn(v.x, v.y);
    p[1] = __floats2half2_rn(v.z, v.w);
}

// ---------------- weights fp32 -> fp16 --------------------------------------------
__global__ void cvt_w(const float* __restrict__ w0, const float* __restrict__ w1,
                      const float* __restrict__ w2, const float* __restrict__ w3,
                      __half* __restrict__ hi)
{
    const int seg = blockIdx.x >> 8;
    const float* w = (seg == 0) ? w0 : (seg == 1) ? w1 : (seg == 2) ? w2 : w3;
    int i = ((blockIdx.x & 255) * blockDim.x + threadIdx.x) * 4;
    float4 v = *(const float4*)(w + i);
    __half2* hp = (__half2*)(hi + seg * NW + i);
    hp[0] = __floats2half2_rn(v.x, v.y);
    hp[1] = __floats2half2_rn(v.z, v.w);
}

// ---------------- gather-attention: both batches per block ----------------------
// One block per n: stages K rows for b=0 AND b=1 (same idx list), 16 warps.
// smem: K 64KB | q 2KB | rows 128B -> 3 blocks/SM x 16 warps = 48 warps/SM.
#define ATT_SMEM (65536 + 2048 + 128)

__global__ __launch_bounds__(512, 3)
void attn_kernel(const __half* __restrict__ Q, const __half* __restrict__ Kt,
                 const __half* __restrict__ V, const int* __restrict__ idx,
                 __half* __restrict__ oh)
{
    extern __shared__ char sm[];
    const uint32_t sbase = smem_u32(sm);
    int* srows = (int*)(sm + 65536 + 2048);
    const int n = blockIdx.x;            // 0 .. SEQN-1
    const int tid = threadIdx.x;
    const int ibase = n * KNN;

    if (tid < KNN) srows[tid] = idx[ibase + tid];

    // stage K for both batches: 64 rows x 1024 B (r = b*32 + key)
    const int lrow = tid >> 6;       // 0..7
    const int lchk = tid & 63;       // 16B chunk in row
    #pragma unroll
    for (int p = 0; p < 8; ++p) {
        const int r = p * 8 + lrow;            // 0..63
        const int bb = r >> 5;                 // batch
        const int row = idx[ibase + (r & 31)];
        const int schk = lchk ^ (r & 7);       // XOR swizzle within 128B groups
        cp16(sbase + (uint32_t)(r * 1024 + schk * 16),
             Kt + ((size_t)(bb * SEQN + row) << 9) + lchk * 8);
    }
    CP_COMMIT();

    const int w    = tid >> 5;           // 0..15
    const int b    = w >> 3;             // batch
    const int h    = w & 7;              // head
    const int lane = tid & 31;
    const int qbase = (b * SEQN + n) * DMODEL + h * DK;
    // Q already LayerNorm'd and pre-scaled by 1/8 in the GEMM epilogue.
    const uint32_t qv = *(const uint32_t*)(Q + qbase + lane * 2);
    *(uint32_t*)(sm + 65536 + w * 128 + lane * 4) = qv;

    CP_WAIT0();
    __syncthreads();

    // score phase: lane = key; 8 x (LDS.128 K swizzled + LDS.128 q broadcast)
    // 4 accumulators to cut the serial fma chain from 64 to 16.
    float s0 = 0.f, s1 = 0.f, s2 = 0.f, s3 = 0.f;
    const char* kbase = sm + (b * 32 + lane) * 1024;
    const char* qb = sm + 65536 + w * 128;
    const int hx = h * 8;
    const int lx = lane & 7;
    #pragma unroll
    for (int i = 0; i < 8; ++i) {
        const uint4 kc = *(const uint4*)(kbase + ((hx + i) ^ lx) * 16);
        const uint4 qc = *(const uint4*)(qb + i * 16);
        float2 k0 = __half22float2(*(const __half2*)&kc.x);
        float2 k1 = __half22float2(*(const __half2*)&kc.y);
        float2 k2 = __half22float2(*(const __half2*)&kc.z);
        float2 k3 = __half22float2(*(const __half2*)&kc.w);
        float2 q0 = __half22float2(*(const __half2*)&qc.x);
        float2 q1 = __half22float2(*(const __half2*)&qc.y);
        float2 q2 = __half22float2(*(const __half2*)&qc.z);
        float2 q3 = __half22float2(*(const __half2*)&qc.w);
        s0 = fmaf(q0.x, k0.x, s0); s0 = fmaf(q0.y, k0.y, s0);
        s1 = fmaf(q1.x, k1.x, s1); s1 = fmaf(q1.y, k1.y, s1);
        s2 = fmaf(q2.x, k2.x, s2); s2 = fmaf(q2.y, k2.y, s2);
        s3 = fmaf(q3.x, k3.x, s3); s3 = fmaf(q3.y, k3.y, s3);
    }
    const float s = (s0 + s1) + (s2 + s3);

    // softmax across the 32 lanes (= 32 keys)
    const float m = warp_max(s);
    const float e = __expf(s - m);
    const float denom = warp_sum(e);
    const float a = e / denom;

    // output phase: lane = dim pair, V read directly from global (L2)
    const __half* vb = V + ((size_t)(b * SEQN) << 9) + h * DK + lane * 2;
    float o0a = 0.f, o0b = 0.f, o1a = 0.f, o1b = 0.f;
    #pragma unroll
    for (int k = 0; k < KNN; k += 2) {
        const float ak0 = __shfl_sync(0xffffffffu, a, k);
        const float ak1 = __shfl_sync(0xffffffffu, a, k + 1);
        const float2 vv0 = __half22float2(
            *(const __half2*)(vb + ((size_t)srows[k] << 9)));
        const float2 vv1 = __half22float2(
            *(const __half2*)(vb + ((size_t)srows[k + 1] << 9)));
        o0a = fmaf(ak0, vv0.x, o0a);
        o1a = fmaf(ak0, vv0.y, o1a);
        o0b = fmaf(ak1, vv1.x, o0b);
        o1b = fmaf(ak1, vv1.y, o1b);
    }
    ((__half2*)(oh + qbase))[lane] = __floats2half2_rn(o0a + o0b, o1a + o1b);
}

// ---------------- launch ---------------------------------------------------------
extern "C" void kernel_launch(void* const* d_in, const int* in_sizes, int n_in,
                              void* d_out, int out_size)
{
    const float* x    = (const float*)d_in[0];
    const int*   idx  = (const int*)  d_in[1];
    const float* Wq   = (const float*)d_in[2];
    const float* Wk   = (const float*)d_in[3];
    const float* Wv   = (const float*)d_in[4];
    const float* Wout = (const float*)d_in[5];
    const float* bout = (const float*)d_in[6];
    float* out = (float*)d_out;

    static __half *gQ = nullptr, *gK, *gV, *xh, *ah, *wh;
    if (!gQ) {
        cudaGetSymbolAddress((void**)&gQ, g_Q);
        cudaGetSymbolAddress((void**)&gK, g_K);
        cudaGetSymbolAddress((void**)&gV, g_V);
        cudaGetSymbolAddress((void**)&xh, g_xh);
        cudaGetSymbolAddress((void**)&ah, g_ah);
        cudaGetSymbolAddress((void**)&wh, g_wh);
        cudaFuncSetAttribute((const void*)gemm_f16<1, 1>,
                             cudaFuncAttributeMaxDynamicSharedMemorySize, GEMM_SMEM);
        cudaFuncSetAttribute((const void*)gemm_f16<0, 0>,
                             cudaFuncAttributeMaxDynamicSharedMemorySize, GEMM_SMEM);
        cudaFuncSetAttribute((const void*)attn_kernel,
                             cudaFuncAttributeMaxDynamicSharedMemorySize, ATT_SMEM);
    }

    // conversions
    cvt_h<<<NX / 1024, 256>>>(x, xh);
    cvt_w<<<1024, 256>>>(Wq, Wk, Wv, Wout, wh);

    // fused Q,K,V projections -> fp16; LN fused for Q (x1/8) and K
    gemm_f16<1, 1><<<dim3(12, 128), 256, GEMM_SMEM>>>(xh, wh, gQ, gK, gV, nullptr);

    // attention: one block per n covers both batches
    attn_kernel<<<SEQN, 512, ATT_SMEM>>>(gQ, gK, gV, idx, ah);

    // output projection + bias -> fp32 d_out
    gemm_f16<0, 0><<<dim3(4, 128), 256, GEMM_SMEM>>>(ah, wh + 3 * (size_t)NW,
                                                     out, out, out, bout);
}